// round 5
// baseline (speedup 1.0000x reference)
#include <cuda_runtime.h>
#include <math.h>

#define NPTS  2048
#define PAIRS 64
#define IVALS 16

// ---- scratch (no allocations allowed) --------------------------------------
__device__ float4   g_y[PAIRS * NPTS];      // transformed source: xyz + |y|^2
__device__ float4   g_x[IVALS * NPTS];      // target prescaled: -2x,-2y,-2z, |x|^2
__device__ unsigned g_colmin[PAIRS * NPTS]; // per-(pair,m) min d2, uint bits
__device__ float    g_rowpart[PAIRS * 16];  // per-(pair,nsplit) row-min sums
__device__ unsigned g_count[PAIRS];         // per-pair block arrival counter

// ---------------------------------------------------------------------------
// Kernel 1: transform source (4 pts/thread, float4 loads), prescale target,
// init colmin + counters. Grid: 128 blocks x 256 thr (1024 pts per block).
// ---------------------------------------------------------------------------
__global__ void __launch_bounds__(256) prep_kernel(const float* __restrict__ src,
                            const float* __restrict__ tgt,
                            const float* __restrict__ rot,
                            const float* __restrict__ trn,
                            const float* __restrict__ scl)
{
    __shared__ float M[13];
    const int pair = blockIdx.x >> 1;
    const int base = (blockIdx.x & 1) * 1024 + threadIdx.x * 4;

    if (threadIdx.x == 0) {
        float ax = rot[pair * 3 + 0], ay = rot[pair * 3 + 1], az = rot[pair * 3 + 2];
        float sx, cx, sy, cy, sz, cz;
        sincosf(ax, &sx, &cx);
        sincosf(ay, &sy, &cy);
        sincosf(az, &sz, &cz);
        M[0] = cy * cz;                M[1] = -cy * sz;               M[2] = sy;
        M[3] = cx * sz + sx * sy * cz; M[4] = cx * cz - sx * sy * sz; M[5] = -sx * cy;
        M[6] = sx * sz - cx * sy * cz; M[7] = sx * cz + cx * sy * sz; M[8] = cx * cy;
        M[9]  = trn[pair * 3 + 0];
        M[10] = trn[pair * 3 + 1];
        M[11] = trn[pair * 3 + 2];
        M[12] = scl[pair];
    }
    if (threadIdx.x == 32 && (blockIdx.x & 1) == 0) g_count[pair] = 0;
    __syncthreads();

    const int idx = pair * NPTS + base;     // multiple of 4 -> float4-aligned *3
    const float4* s4 = (const float4*)(src + (size_t)idx * 3);
    const float4 A = s4[0], B = s4[1], C = s4[2];
    const float px[4] = {A.x, A.w, B.z, C.y};
    const float py[4] = {A.y, B.x, B.w, C.z};
    const float pz[4] = {A.z, B.y, C.x, C.w};
    const float s = M[12];

#pragma unroll
    for (int k = 0; k < 4; k++) {
        float qx = s * fmaf(M[0], px[k], fmaf(M[1], py[k], fmaf(M[2], pz[k], M[9])));
        float qy = s * fmaf(M[3], px[k], fmaf(M[4], py[k], fmaf(M[5], pz[k], M[10])));
        float qz = s * fmaf(M[6], px[k], fmaf(M[7], py[k], fmaf(M[8], pz[k], M[11])));
        g_y[idx + k] = make_float4(qx, qy, qz, qx * qx + qy * qy + qz * qz);
    }
    *(uint4*)&g_colmin[idx] = make_uint4(0x7F800000u, 0x7F800000u,
                                         0x7F800000u, 0x7F800000u);

    if (pair < IVALS) {
        const float4* t4 = (const float4*)(tgt + (size_t)idx * 3);
        const float4 D = t4[0], E = t4[1], F = t4[2];
        const float bx[4] = {D.x, D.w, E.z, F.y};
        const float by[4] = {D.y, E.x, E.w, F.z};
        const float bz[4] = {D.z, E.y, F.x, F.w};
#pragma unroll
        for (int k = 0; k < 4; k++) {
            g_x[idx + k] = make_float4(-2.0f * bx[k], -2.0f * by[k], -2.0f * bz[k],
                                       bx[k] * bx[k] + by[k] * by[k] + bz[k] * bz[k]);
        }
    }
}

// ---------------------------------------------------------------------------
// Kernel 2: bidirectional chamfer + fused per-pair finalize.
// Block (nsplit, pair): 128 target rows (registers) x 2048 source cols,
// streamed in 8 chunks of 256 via shared. Thread (tn,tm): 8 rows x 16 cols.
//   c  = fma(xx,yx, fma(xy,yy, fma(xz,yz, yw)))    // |y|^2 - 2 x.y
//   rowmin over c (x2 deferred), colmin over c + x2.
// Last block per pair (atomic counter) computes the pair's output.
// ---------------------------------------------------------------------------
__global__ void __launch_bounds__(256, 2) chamfer_kernel(float* __restrict__ out)
{
    const int pair   = blockIdx.y;
    const int nsplit = blockIdx.x;
    const int t  = threadIdx.x;
    const int tn = t >> 4;
    const int tm = t & 15;

    __shared__ float4 s_y[256];
    __shared__ float  s_red[16][257];
    __shared__ float  s_sum[8];
    __shared__ int    s_last;

    const float4* gx = g_x + (pair & 15) * NPTS + nsplit * 128;
    const float4* gy = g_y + pair * NPTS;
    unsigned* cmin = g_colmin + pair * NPTS;

    float4 xf[8];
#pragma unroll
    for (int i = 0; i < 8; i++) xf[i] = gx[tn * 8 + i];

    float rm[8];
#pragma unroll
    for (int i = 0; i < 8; i++) rm[i] = 3.4e38f;

    for (int chunk = 0; chunk < 8; chunk++) {
        const int mbase = chunk * 256;

        __syncthreads();                 // prior chunk's s_y/s_red reads done
        s_y[t] = gy[mbase + t];
        __syncthreads();                 // s_y ready

        float cm[16];
#pragma unroll
        for (int j = 0; j < 16; j++) cm[j] = 3.4e38f;

#pragma unroll
        for (int jj = 0; jj < 16; jj++) {
            const float4 y = s_y[tm + 16 * jj];
#pragma unroll
            for (int i = 0; i < 8; i++) {
                float c = fmaf(xf[i].x, y.x,
                          fmaf(xf[i].y, y.y,
                          fmaf(xf[i].z, y.z, y.w)));
                rm[i]  = fminf(rm[i], c);
                cm[jj] = fminf(cm[jj], c + xf[i].w);
            }
        }

        // flush col-mins: reduce over tn (16 partials per column), atomicMin
#pragma unroll
        for (int jj = 0; jj < 16; jj++) s_red[tn][tm + 16 * jj] = cm[jj];
        __syncthreads();
        float v = s_red[0][t];
#pragma unroll
        for (int k = 1; k < 16; k++) v = fminf(v, s_red[k][t]);
        v = fmaxf(v, 0.0f);              // d2 >= 0: keep uint ordering monotone
        atomicMin(&cmin[mbase + t], __float_as_uint(v));
    }

    // finalize row mins: add deferred x2, reduce over tm, sum 128 rows
    __syncthreads();
#pragma unroll
    for (int i = 0; i < 8; i++) s_red[tm][tn * 8 + i] = rm[i] + xf[i].w;
    __syncthreads();

    float total = 0.0f;
    if (t < 128) {
        float v = s_red[0][t];
#pragma unroll
        for (int k = 1; k < 16; k++) v = fminf(v, s_red[k][t]);
        total = v;
    }
#pragma unroll
    for (int off = 16; off > 0; off >>= 1)
        total += __shfl_down_sync(0xffffffffu, total, off);
    if ((t & 31) == 0) s_sum[t >> 5] = total;
    __syncthreads();
    if (t == 0) {
        g_rowpart[pair * 16 + nsplit] =
            s_sum[0] + s_sum[1] + s_sum[2] + s_sum[3] +
            s_sum[4] + s_sum[5] + s_sum[6] + s_sum[7];
    }

    // -------- fused finalize: last block of this pair computes the output ---
    __threadfence();                     // order rowpart STG + colmin atomics
    __syncthreads();                     // all threads' fences precede the add
    if (t == 0) s_last = (atomicAdd(&g_count[pair], 1u) == 15u);
    __syncthreads();
    if (!s_last) return;

    float local = 0.0f;
#pragma unroll
    for (int k = 0; k < 8; k++)
        local += __uint_as_float(__ldcg(&cmin[t + 256 * k]));
    if (t < 16) local += __ldcg(&g_rowpart[pair * 16 + t]);

    float* sbuf = &s_red[0][0];          // reuse shared
    sbuf[t] = local;
    __syncthreads();
#pragma unroll
    for (int s = 128; s > 0; s >>= 1) {
        if (t < s) sbuf[t] += sbuf[t + s];
        __syncthreads();
    }
    if (t == 0) out[pair] = sbuf[0] * (1.0f / 2048.0f);
}

// ---------------------------------------------------------------------------
extern "C" void kernel_launch(void* const* d_in, const int* in_sizes, int n_in,
                              void* d_out, int out_size)
{
    const float* src = (const float*)d_in[0];   // [4,16,2048,3]
    const float* tgt = (const float*)d_in[1];   // [16,2048,3]
    const float* rot = (const float*)d_in[2];   // [4,16,3]
    const float* trn = (const float*)d_in[3];   // [4,16,3]
    const float* scl = (const float*)d_in[4];   // [4,16]
    (void)in_sizes; (void)n_in; (void)out_size;

    prep_kernel<<<128, 256>>>(src, tgt, rot, trn, scl);
    chamfer_kernel<<<dim3(16, PAIRS), 256>>>((float*)d_out);
}

// round 6
// speedup vs baseline: 1.0676x; 1.0676x over previous
#include <cuda_runtime.h>
#include <math.h>

#define NPTS  2048
#define PAIRS 64
#define IVALS 16

// ---- scratch (no allocations allowed) --------------------------------------
__device__ float4   g_y[PAIRS * NPTS];      // transformed source: xyz + |y|^2
__device__ float4   g_x[IVALS * NPTS];      // target prescaled: -2x,-2y,-2z, |x|^2
__device__ unsigned g_colmin[PAIRS * NPTS]; // per-(pair,m) min d2, uint bits
__device__ float    g_rowpart[PAIRS * 16];  // per-(pair,nsplit) row-min sums

// ---------------------------------------------------------------------------
// Kernel 1: transform source (4 pts/thread, float4 loads), prescale target,
// init colmin. Grid: 128 blocks x 256 thr (1024 pts per block).
// ---------------------------------------------------------------------------
__global__ void __launch_bounds__(256) prep_kernel(const float* __restrict__ src,
                            const float* __restrict__ tgt,
                            const float* __restrict__ rot,
                            const float* __restrict__ trn,
                            const float* __restrict__ scl)
{
    __shared__ float M[13];
    const int pair = blockIdx.x >> 1;
    const int base = (blockIdx.x & 1) * 1024 + threadIdx.x * 4;

    if (threadIdx.x == 0) {
        float ax = rot[pair * 3 + 0], ay = rot[pair * 3 + 1], az = rot[pair * 3 + 2];
        float sx, cx, sy, cy, sz, cz;
        sincosf(ax, &sx, &cx);
        sincosf(ay, &sy, &cy);
        sincosf(az, &sz, &cz);
        M[0] = cy * cz;                M[1] = -cy * sz;               M[2] = sy;
        M[3] = cx * sz + sx * sy * cz; M[4] = cx * cz - sx * sy * sz; M[5] = -sx * cy;
        M[6] = sx * sz - cx * sy * cz; M[7] = sx * cz + cx * sy * sz; M[8] = cx * cy;
        M[9]  = trn[pair * 3 + 0];
        M[10] = trn[pair * 3 + 1];
        M[11] = trn[pair * 3 + 2];
        M[12] = scl[pair];
    }
    __syncthreads();

    const int idx = pair * NPTS + base;     // multiple of 4 -> 16B-aligned *3
    const float4* s4 = (const float4*)(src + (size_t)idx * 3);
    const float4 A = s4[0], B = s4[1], C = s4[2];
    const float px[4] = {A.x, A.w, B.z, C.y};
    const float py[4] = {A.y, B.x, B.w, C.z};
    const float pz[4] = {A.z, B.y, C.x, C.w};
    const float s = M[12];

#pragma unroll
    for (int k = 0; k < 4; k++) {
        float qx = s * fmaf(M[0], px[k], fmaf(M[1], py[k], fmaf(M[2], pz[k], M[9])));
        float qy = s * fmaf(M[3], px[k], fmaf(M[4], py[k], fmaf(M[5], pz[k], M[10])));
        float qz = s * fmaf(M[6], px[k], fmaf(M[7], py[k], fmaf(M[8], pz[k], M[11])));
        g_y[idx + k] = make_float4(qx, qy, qz, qx * qx + qy * qy + qz * qz);
    }
    *(uint4*)&g_colmin[idx] = make_uint4(0x7F800000u, 0x7F800000u,
                                         0x7F800000u, 0x7F800000u);

    if (pair < IVALS) {
        const float4* t4 = (const float4*)(tgt + (size_t)idx * 3);
        const float4 D = t4[0], E = t4[1], F = t4[2];
        const float bx[4] = {D.x, D.w, E.z, F.y};
        const float by[4] = {D.y, E.x, E.w, F.z};
        const float bz[4] = {D.z, E.y, F.x, F.w};
#pragma unroll
        for (int k = 0; k < 4; k++) {
            g_x[idx + k] = make_float4(-2.0f * bx[k], -2.0f * by[k], -2.0f * bz[k],
                                       bx[k] * bx[k] + by[k] * by[k] + bz[k] * bz[k]);
        }
    }
}

// ---------------------------------------------------------------------------
// Kernel 2: bidirectional chamfer. Lean 8x8 tile, 3 CTAs/SM target.
// Block (nsplit, pair): 128 target rows x 2048 source cols, 16 chunks of 128.
// Thread (tn 0..15, tm 0..15): 8 rows x 8 cols.
//   d2 = x2 + fma(xx,yx, fma(xy,yy, fma(xz,yz, yw)))   // |x-y|^2
// Both row-min and col-min accumulate d2 directly.
// ---------------------------------------------------------------------------
__global__ void __launch_bounds__(256, 3) chamfer_kernel()
{
    const int pair   = blockIdx.y;
    const int nsplit = blockIdx.x;
    const int t  = threadIdx.x;
    const int tn = t >> 4;
    const int tm = t & 15;

    __shared__ float4 s_y[128];
    __shared__ float  s_red[16][129];
    __shared__ float  s_sum[8];

    const float4* gx = g_x + (pair & 15) * NPTS + nsplit * 128;
    const float4* gy = g_y + pair * NPTS;
    unsigned* cmin = g_colmin + pair * NPTS;

    float4 xf[8];
#pragma unroll
    for (int i = 0; i < 8; i++) xf[i] = gx[tn * 8 + i];

    float rm[8];
#pragma unroll
    for (int i = 0; i < 8; i++) rm[i] = 3.4e38f;

    for (int chunk = 0; chunk < 16; chunk++) {
        const int mbase = chunk * 128;

        __syncthreads();                 // prior chunk's s_y/s_red reads done
        if (t < 128) s_y[t] = gy[mbase + t];
        __syncthreads();                 // s_y ready

        float cm[8];
#pragma unroll
        for (int j = 0; j < 8; j++) cm[j] = 3.4e38f;

#pragma unroll
        for (int jj = 0; jj < 8; jj++) {
            const float4 y = s_y[tm + 16 * jj];
#pragma unroll
            for (int i = 0; i < 8; i++) {
                float d2 = xf[i].w +
                           fmaf(xf[i].x, y.x,
                           fmaf(xf[i].y, y.y,
                           fmaf(xf[i].z, y.z, y.w)));
                rm[i]  = fminf(rm[i], d2);
                cm[jj] = fminf(cm[jj], d2);
            }
        }

        // flush col-mins: reduce over tn, then global atomicMin
#pragma unroll
        for (int jj = 0; jj < 8; jj++) s_red[tn][tm + 16 * jj] = cm[jj];
        __syncthreads();
        if (t < 128) {
            float v = s_red[0][t];
#pragma unroll
            for (int k = 1; k < 16; k++) v = fminf(v, s_red[k][t]);
            v = fmaxf(v, 0.0f);          // d2 >= 0: keep uint ordering monotone
            atomicMin(&cmin[mbase + t], __float_as_uint(v));
        }
    }

    // finalize row mins: reduce over tm, then sum the 128 rows
    __syncthreads();
#pragma unroll
    for (int i = 0; i < 8; i++) s_red[tm][tn * 8 + i] = rm[i];
    __syncthreads();

    float total = 0.0f;
    if (t < 128) {
        float v = s_red[0][t];
#pragma unroll
        for (int k = 1; k < 16; k++) v = fminf(v, s_red[k][t]);
        total = v;
    }
#pragma unroll
    for (int off = 16; off > 0; off >>= 1)
        total += __shfl_down_sync(0xffffffffu, total, off);
    if ((t & 31) == 0) s_sum[t >> 5] = total;
    __syncthreads();
    if (t == 0) {
        g_rowpart[pair * 16 + nsplit] =
            s_sum[0] + s_sum[1] + s_sum[2] + s_sum[3] +
            s_sum[4] + s_sum[5] + s_sum[6] + s_sum[7];
    }
}

// ---------------------------------------------------------------------------
// Kernel 3: per-pair means and combine
// ---------------------------------------------------------------------------
__global__ void final_kernel(float* __restrict__ out)
{
    const int pair = blockIdx.x;
    const int t = threadIdx.x;
    float local = 0.0f;
#pragma unroll
    for (int k = 0; k < 8; k++)
        local += __uint_as_float(g_colmin[pair * NPTS + t + 256 * k]);
    if (t < 16) local += g_rowpart[pair * 16 + t];

    __shared__ float sbuf[256];
    sbuf[t] = local;
    __syncthreads();
#pragma unroll
    for (int s = 128; s > 0; s >>= 1) {
        if (t < s) sbuf[t] += sbuf[t + s];
        __syncthreads();
    }
    if (t == 0) out[pair] = sbuf[0] * (1.0f / 2048.0f);
}

// ---------------------------------------------------------------------------
extern "C" void kernel_launch(void* const* d_in, const int* in_sizes, int n_in,
                              void* d_out, int out_size)
{
    const float* src = (const float*)d_in[0];   // [4,16,2048,3]
    const float* tgt = (const float*)d_in[1];   // [16,2048,3]
    const float* rot = (const float*)d_in[2];   // [4,16,3]
    const float* trn = (const float*)d_in[3];   // [4,16,3]
    const float* scl = (const float*)d_in[4];   // [4,16]
    (void)in_sizes; (void)n_in; (void)out_size;

    prep_kernel<<<128, 256>>>(src, tgt, rot, trn, scl);
    chamfer_kernel<<<dim3(16, PAIRS), 256>>>();
    final_kernel<<<PAIRS, 256>>>((float*)d_out);
}